// round 1
// baseline (speedup 1.0000x reference)
#include <cuda_runtime.h>
#include <cstdint>

// Problem constants (fixed by the dataset)
#define NC   1000      // cells
#define NGOI 500       // genes of interest
#define NGT  5000      // total genes
#define NL   10        // latent dim
#define NK   129       // knots (NBINS+1)
#define RS   132       // padded row stride (16B-aligned float4 rows)
#define NPAIR (NC*NGOI)

#define MAIN_BLOCKS 1184
#define MAIN_THREADS 256

// ---------------- device scratch (static: no allocation allowed) -------------
__device__ float  g_logits[NC * NGT];                 // 20 MB
__device__ float  g_lse[NC];
__device__ float  g_base[NGOI * RS];                  // 264 KB padded baseline rows
__device__ float  g_delta[(size_t)NPAIR * RS];        // 264 MB height deltas
__device__ double g_part[MAIN_BLOCKS];

// ---------------- kernel: pad spline_baseline rows for genes_oi --------------
__global__ void k_padbase(const float* __restrict__ sb, const int* __restrict__ goi) {
    int j = blockIdx.x;                 // local gene index
    int gene = goi[j];
    int t = threadIdx.x;
    if (t < NK) g_base[j * RS + t] = sb[(size_t)gene * NK + t];
}

// ---------------- kernel: overall logits [NC x NGT] --------------------------
__global__ void k_logits(const float* __restrict__ latent,
                         const float* __restrict__ wo,
                         const float* __restrict__ ob) {
    __shared__ float lat[16 * NL];
    int g  = blockIdx.x * 256 + threadIdx.x;
    int c0 = blockIdx.y * 16;
    int t = threadIdx.x;
    if (t < 16 * NL) {
        int cc = c0 + t / NL;
        lat[t] = (cc < NC) ? latent[cc * NL + t % NL] : 0.f;
    }
    __syncthreads();
    if (g >= NGT) return;
    float w[NL];
#pragma unroll
    for (int l = 0; l < NL; l++) w[l] = wo[g * NL + l];
    float base = ob[g];
    int cmax = NC - c0; if (cmax > 16) cmax = 16;
    for (int c = 0; c < cmax; c++) {
        float a = base;
#pragma unroll
        for (int l = 0; l < NL; l++) a = fmaf(lat[c * NL + l], w[l], a);
        g_logits[(c0 + c) * NGT + g] = a;
    }
}

// ---------------- kernel: per-cell log-sum-exp over genes --------------------
__global__ void k_lse() {
    int c = blockIdx.x;
    float s = 0.f;
    for (int g = threadIdx.x; g < NGT; g += 256)
        s += __expf(g_logits[c * NGT + g]);
    __shared__ float sh[8];
#pragma unroll
    for (int o = 16; o; o >>= 1) s += __shfl_xor_sync(0xffffffffu, s, o);
    if ((threadIdx.x & 31) == 0) sh[threadIdx.x >> 5] = s;
    __syncthreads();
    if (threadIdx.x < 8) {
        s = sh[threadIdx.x];
#pragma unroll
        for (int o = 4; o; o >>= 1) s += __shfl_xor_sync(0xffu, s, o);
        if (threadIdx.x == 0) g_lse[c] = __logf(s);
    }
}

// ---------------- kernel: height deltas per (cell, local-gene) pair ----------
// delta[c*NGOI+j][k] = sum_l latent[c][l] * hw[genes_oi[j]][l][k]
__global__ void __launch_bounds__(256) k_delta(const float* __restrict__ latent,
                                               const float* __restrict__ hw,
                                               const int*   __restrict__ goi) {
    __shared__ float W[NL * RS];
    int j = blockIdx.x;
    int gene = goi[j];
    for (int i = threadIdx.x; i < NL * NK; i += 256) {
        int l = i / NK, k = i - l * NK;
        W[l * RS + k] = hw[(size_t)gene * NL * NK + i];
    }
    __syncthreads();
    int w = threadIdx.x >> 5, lane = threadIdx.x & 31;
    int c = blockIdx.y * 8 + w;
    if (c >= NC) return;
    float s[NL];
#pragma unroll
    for (int l = 0; l < NL; l++) s[l] = latent[c * NL + l];
    float4 acc = make_float4(0.f, 0.f, 0.f, 0.f);
    float a128 = 0.f;
    int k4 = lane * 4;
#pragma unroll
    for (int l = 0; l < NL; l++) {
        float4 wv = *(const float4*)&W[l * RS + k4];
        acc.x = fmaf(s[l], wv.x, acc.x);
        acc.y = fmaf(s[l], wv.y, acc.y);
        acc.z = fmaf(s[l], wv.z, acc.z);
        acc.w = fmaf(s[l], wv.w, acc.w);
        a128  = fmaf(s[l], W[l * RS + 128], a128);
    }
    size_t p = (size_t)c * NGOI + j;
    *(float4*)&g_delta[p * RS + k4] = acc;
    if (lane == 0) g_delta[p * RS + 128] = a128;
}

// ---------------- kernel: per-cut spline log-prob + overall, summed ----------
__global__ void __launch_bounds__(MAIN_THREADS) k_main(
        const float* __restrict__ coord,
        const int*   __restrict__ cxg,    // pair index [0, NPAIR)
        const int*   __restrict__ lcxg,   // cell x total-gene index [0, NC*NGT)
        const int*   __restrict__ gloc,   // local gene index [0, NGOI)
        int ncuts) {
    int w = threadIdx.x >> 5, lane = threadIdx.x & 31;
    int gw = blockIdx.x * (MAIN_THREADS >> 5) + w;
    int nw = gridDim.x * (MAIN_THREADS >> 5);
    double acc = 0.0;
    const float C = 4.852030263919617f + 8.517193191416238f; // ln(128)+ln(5000)

    for (int i = gw; i < ncuts; i += nw) {
        int   p  = cxg[i];
        int   gl = gloc[i];
        int   q  = lcxg[i];
        float x  = coord[i];
        int cell = q / NGT;

        size_t db = (size_t)p * RS;
        const float4 d = *(const float4*)&g_delta[db + lane * 4];
        const float4 b = *(const float4*)&g_base[gl * RS + lane * 4];
        float logit = g_logits[q];
        float lse   = g_lse[cell];

        float4 u;
        u.x = __expf(d.x + b.x);
        u.y = __expf(d.y + b.y);
        u.z = __expf(d.z + b.z);
        u.w = __expf(d.w + b.w);
        float s = u.x + u.y + u.z + u.w;
        float u128 = 0.f;
        if (lane == 31) {
            u128 = __expf(g_delta[db + 128] + g_base[gl * RS + 128]);
            s += 0.5f * u128;          // add full, then endpoint halves
        }
        if (lane == 0) s -= 0.5f * u.x;

        float xs = fminf(fmaxf(x, 0.f), 0.999999f) * 128.f;
        int bi = (int)xs; if (bi > 127) bi = 127;
        float alpha = xs - (float)bi;

        int lb = bi >> 2, cb = bi & 3;
        int rk = bi + 1;
        float L = 0.f, R = 0.f;
        if (lane == lb) L = (cb == 0) ? u.x : (cb == 1) ? u.y : (cb == 2) ? u.z : u.w;
        if (rk == 128) {
            if (lane == 31) R = u128;
        } else {
            int lr = rk >> 2, cr = rk & 3;
            if (lane == lr) R = (cr == 0) ? u.x : (cr == 1) ? u.y : (cr == 2) ? u.z : u.w;
        }
#pragma unroll
        for (int o = 16; o; o >>= 1) {
            s += __shfl_xor_sync(0xffffffffu, s, o);
            L += __shfl_xor_sync(0xffffffffu, L, o);
            R += __shfl_xor_sync(0xffffffffu, R, o);
        }
        if (lane == 0) {
            float val = __logf(fmaf(alpha, R - L, L)) - __logf(s) + C + logit - lse;
            acc += (double)val;
        }
    }

    __shared__ double sh[MAIN_THREADS / 32];
    if (lane == 0) sh[w] = acc;
    __syncthreads();
    if (threadIdx.x == 0) {
        double t = 0.0;
        for (int k = 0; k < MAIN_THREADS / 32; k++) t += sh[k];
        g_part[blockIdx.x] = t;
    }
}

// ---------------- kernel: deterministic final reduce -------------------------
__global__ void k_final(float* __restrict__ out) {
    __shared__ double sh[256];
    double t = 0.0;
    for (int i = threadIdx.x; i < MAIN_BLOCKS; i += 256) t += g_part[i];
    sh[threadIdx.x] = t;
    __syncthreads();
    for (int s = 128; s; s >>= 1) {
        if (threadIdx.x < s) sh[threadIdx.x] += sh[threadIdx.x + s];
        __syncthreads();
    }
    if (threadIdx.x == 0) out[0] = (float)(-sh[0]);   // elbo = -sum(likelihood)
}

// ---------------- launch ------------------------------------------------------
extern "C" void kernel_launch(void* const* d_in, const int* in_sizes, int n_in,
                              void* d_out, int out_size) {
    const float* latent = (const float*)d_in[0];
    const float* coord  = (const float*)d_in[1];
    const int*   goi    = (const int*)  d_in[2];
    const int*   cxg    = (const int*)  d_in[3];   // cut_local_cellxgene_ix
    const int*   lcxg   = (const int*)  d_in[4];   // cut_localcellxgene_ix
    const int*   gloc   = (const int*)  d_in[5];   // cut_local_gene_ix
    const float* hw     = (const float*)d_in[6];   // height_slope_w
    const float* wo     = (const float*)d_in[7];   // overall_slope_w
    const float* ob     = (const float*)d_in[8];   // overall_baseline
    const float* sb     = (const float*)d_in[9];   // spline_baseline
    float* out = (float*)d_out;
    int ncuts = in_sizes[1];

    k_padbase<<<NGOI, 160>>>(sb, goi);
    {
        dim3 grid((NGT + 255) / 256, (NC + 15) / 16);
        k_logits<<<grid, 256>>>(latent, wo, ob);
    }
    k_lse<<<NC, 256>>>();
    {
        dim3 grid(NGOI, (NC + 7) / 8);
        k_delta<<<grid, 256>>>(latent, hw, goi);
    }
    k_main<<<MAIN_BLOCKS, MAIN_THREADS>>>(coord, cxg, lcxg, gloc, ncuts);
    k_final<<<1, 256>>>(out);
}

// round 2
// speedup vs baseline: 1.4102x; 1.4102x over previous
#include <cuda_runtime.h>
#include <cuda_fp16.h>
#include <cstdint>

// Problem constants (fixed by the dataset)
#define NC   1000      // cells
#define NGOI 500       // genes of interest
#define NGT  5000      // total genes
#define NL   10        // latent dim
#define NK   129       // knots (NBINS+1)
#define RSH  132       // padded delta row stride in halves (8B-aligned lanes)
#define RSB  132       // padded baseline row stride in floats
#define NPAIR (NC*NGOI)

#define MAIN_BLOCKS 1184
#define MAIN_THREADS 256
#define CSPLIT 8              // cell splits in k_delta
#define CPB (NC / CSPLIT)     // 125 cells per block

// ---------------- device scratch (static: no allocation allowed) -------------
__device__ float  g_logits[NC * NGT];                    // 20 MB
__device__ float  g_lse[NC];
__device__ float  g_base[NGOI * RSB];                    // padded baseline rows (f32)
__device__ __half g_delta[(size_t)NPAIR * RSH];          // 132 MB height deltas (fp16)
__device__ double g_part[MAIN_BLOCKS];

// ---------------- kernel: pad spline_baseline rows for genes_oi --------------
__global__ void k_padbase(const float* __restrict__ sb, const int* __restrict__ goi) {
    int j = blockIdx.x;
    int gene = goi[j];
    int t = threadIdx.x;
    if (t < NK) g_base[j * RSB + t] = sb[(size_t)gene * NK + t];
}

// ---------------- kernel: overall logits [NC x NGT] --------------------------
__global__ void k_logits(const float* __restrict__ latent,
                         const float* __restrict__ wo,
                         const float* __restrict__ ob) {
    __shared__ float lat[16 * NL];
    int g  = blockIdx.x * 256 + threadIdx.x;
    int c0 = blockIdx.y * 16;
    int t = threadIdx.x;
    if (t < 16 * NL) {
        int cc = c0 + t / NL;
        lat[t] = (cc < NC) ? latent[cc * NL + t % NL] : 0.f;
    }
    __syncthreads();
    if (g >= NGT) return;
    float w[NL];
#pragma unroll
    for (int l = 0; l < NL; l++) w[l] = wo[g * NL + l];
    float base = ob[g];
    int cmax = NC - c0; if (cmax > 16) cmax = 16;
    for (int c = 0; c < cmax; c++) {
        float a = base;
#pragma unroll
        for (int l = 0; l < NL; l++) a = fmaf(lat[c * NL + l], w[l], a);
        g_logits[(c0 + c) * NGT + g] = a;
    }
}

// ---------------- kernel: per-cell log-sum-exp over genes --------------------
__global__ void k_lse() {
    int c = blockIdx.x;
    float s = 0.f;
    for (int g = threadIdx.x; g < NGT; g += 256)
        s += __expf(g_logits[c * NGT + g]);
    __shared__ float sh[8];
#pragma unroll
    for (int o = 16; o; o >>= 1) s += __shfl_xor_sync(0xffffffffu, s, o);
    if ((threadIdx.x & 31) == 0) sh[threadIdx.x >> 5] = s;
    __syncthreads();
    if (threadIdx.x < 8) {
        s = sh[threadIdx.x];
#pragma unroll
        for (int o = 4; o; o >>= 1) s += __shfl_xor_sync(0xffu, s, o);
        if (threadIdx.x == 0) g_lse[c] = __logf(s);
    }
}

// ---------------- kernel: height deltas per (cell, local-gene) pair ----------
// delta[c*NGOI+j][k] = sum_l latent[c][l] * hw[genes_oi[j]][l][k]
// One gene per blockIdx.x; W held in registers per lane (lane owns 4 knots).
__global__ void __launch_bounds__(256) k_delta(const float* __restrict__ latent,
                                               const float* __restrict__ hw,
                                               const int*   __restrict__ goi) {
    __shared__ float slat[CPB * 12];        // latent slice, stride 12 (16B aligned)
    int j = blockIdx.x;
    int gene = goi[j];
    int c0 = blockIdx.y * CPB;
    int tid = threadIdx.x;
    int w = tid >> 5, lane = tid & 31;

    // stage latent slice into smem
    for (int i = tid; i < CPB * NL; i += 256) {
        int cc = i / NL, l = i - cc * NL;
        slat[cc * 12 + l] = latent[(c0 + cc) * NL + l];
    }

    // W registers: lane owns knots lane*4..lane*4+3; knot 128 redundant on all lanes
    const float* wp = hw + (size_t)gene * NL * NK;
    float W0[NL], W1[NL], W2[NL], W3[NL], W4[NL];
    int k4 = lane * 4;
#pragma unroll
    for (int l = 0; l < NL; l++) {
        const float* r = wp + l * NK;
        W0[l] = r[k4];  W1[l] = r[k4 + 1];
        W2[l] = r[k4 + 2]; W3[l] = r[k4 + 3];
        W4[l] = r[128];
    }
    __syncthreads();

    for (int c = w; c < CPB; c += 8) {
        const float4 la = *(const float4*)&slat[c * 12];
        const float4 lb = *(const float4*)&slat[c * 12 + 4];
        const float2 lc = *(const float2*)&slat[c * 12 + 8];
        float lv[NL] = {la.x, la.y, la.z, la.w, lb.x, lb.y, lb.z, lb.w, lc.x, lc.y};
        float a0 = 0.f, a1 = 0.f, a2 = 0.f, a3 = 0.f, a4 = 0.f;
#pragma unroll
        for (int l = 0; l < NL; l++) {
            a0 = fmaf(lv[l], W0[l], a0);
            a1 = fmaf(lv[l], W1[l], a1);
            a2 = fmaf(lv[l], W2[l], a2);
            a3 = fmaf(lv[l], W3[l], a3);
            a4 = fmaf(lv[l], W4[l], a4);
        }
        size_t p = (size_t)(c0 + c) * NGOI + j;
        __half2 h01 = __floats2half2_rn(a0, a1);
        __half2 h23 = __floats2half2_rn(a2, a3);
        uint2 st;
        st.x = *(const unsigned*)&h01;
        st.y = *(const unsigned*)&h23;
        *(uint2*)&g_delta[p * RSH + k4] = st;
        if (lane == 31) g_delta[p * RSH + 128] = __float2half_rn(a4);
    }
}

// ---------------- kernel: per-cut spline log-prob + overall, summed ----------
__global__ void __launch_bounds__(MAIN_THREADS) k_main(
        const float* __restrict__ coord,
        const int*   __restrict__ cxg,    // pair index [0, NPAIR)
        const int*   __restrict__ lcxg,   // cell x total-gene index [0, NC*NGT)
        const int*   __restrict__ gloc,   // local gene index [0, NGOI)
        int ncuts) {
    int w = threadIdx.x >> 5, lane = threadIdx.x & 31;
    int gw = blockIdx.x * (MAIN_THREADS >> 5) + w;
    int nw = gridDim.x * (MAIN_THREADS >> 5);
    double acc = 0.0;
    const float C = 4.852030263919617f + 8.517193191416238f; // ln(128)+ln(5000)
    const unsigned FULL = 0xffffffffu;

    for (int i = gw; i < ncuts; i += nw) {
        int   p  = __ldg(&cxg[i]);
        int   gl = __ldg(&gloc[i]);
        int   q  = __ldg(&lcxg[i]);
        float x  = __ldg(&coord[i]);
        int cell = q / NGT;

        size_t db = (size_t)p * RSH;
        uint2 dr = *(const uint2*)&g_delta[db + lane * 4];
        __half2 h01 = *(const __half2*)&dr.x;
        __half2 h23 = *(const __half2*)&dr.y;
        float2 d01 = __half22float2(h01);
        float2 d23 = __half22float2(h23);
        float  d128 = __half2float(g_delta[db + 128]);     // broadcast load
        const float4 b = *(const float4*)&g_base[gl * RSB + lane * 4];
        float  b128 = g_base[gl * RSB + 128];              // broadcast load
        float logit = g_logits[q];
        float lse   = g_lse[cell];

        float ux = __expf(d01.x + b.x);
        float uy = __expf(d01.y + b.y);
        float uz = __expf(d23.x + b.z);
        float uw = __expf(d23.y + b.w);
        float u128 = __expf(d128 + b128);                  // redundant on all lanes

        float s = ux + uy + uz + uw;
        if (lane == 31) s += 0.5f * u128;                  // add top endpoint (half)
        if (lane == 0)  s -= 0.5f * ux;                    // halve bottom endpoint

        float xs = fminf(fmaxf(x, 0.f), 0.999999f) * 128.f;
        int bi = (int)xs; if (bi > 127) bi = 127;
        float alpha = xs - (float)bi;

        // owner-lane fetch of left/right knot pdf values (lb, lr warp-uniform)
        int lb = bi >> 2, cb = bi & 3;
        int rk = bi + 1;
        int lr = (rk == 128) ? 31 : (rk >> 2);
        int cr = rk & 3;
        float selL = (cb == 0) ? ux : (cb == 1) ? uy : (cb == 2) ? uz : uw;
        float selR = (cr == 0) ? ux : (cr == 1) ? uy : (cr == 2) ? uz : uw;
        if (rk == 128) selR = u128;
        float L = __shfl_sync(FULL, selL, lb);
        float R = __shfl_sync(FULL, selR, lr);

#pragma unroll
        for (int o = 16; o; o >>= 1) s += __shfl_xor_sync(FULL, s, o);

        if (lane == 0) {
            float val = __logf(fmaf(alpha, R - L, L)) - __logf(s) + C + logit - lse;
            acc += (double)val;
        }
    }

    __shared__ double sh[MAIN_THREADS / 32];
    if (lane == 0) sh[w] = acc;
    __syncthreads();
    if (threadIdx.x == 0) {
        double t = 0.0;
        for (int k = 0; k < MAIN_THREADS / 32; k++) t += sh[k];
        g_part[blockIdx.x] = t;
    }
}

// ---------------- kernel: deterministic final reduce -------------------------
__global__ void k_final(float* __restrict__ out) {
    __shared__ double sh[256];
    double t = 0.0;
    for (int i = threadIdx.x; i < MAIN_BLOCKS; i += 256) t += g_part[i];
    sh[threadIdx.x] = t;
    __syncthreads();
    for (int s = 128; s; s >>= 1) {
        if (threadIdx.x < s) sh[threadIdx.x] += sh[threadIdx.x + s];
        __syncthreads();
    }
    if (threadIdx.x == 0) out[0] = (float)(-sh[0]);   // elbo = -sum(likelihood)
}

// ---------------- launch ------------------------------------------------------
extern "C" void kernel_launch(void* const* d_in, const int* in_sizes, int n_in,
                              void* d_out, int out_size) {
    const float* latent = (const float*)d_in[0];
    const float* coord  = (const float*)d_in[1];
    const int*   goi    = (const int*)  d_in[2];
    const int*   cxg    = (const int*)  d_in[3];   // cut_local_cellxgene_ix
    const int*   lcxg   = (const int*)  d_in[4];   // cut_localcellxgene_ix
    const int*   gloc   = (const int*)  d_in[5];   // cut_local_gene_ix
    const float* hw     = (const float*)d_in[6];   // height_slope_w
    const float* wo     = (const float*)d_in[7];   // overall_slope_w
    const float* ob     = (const float*)d_in[8];   // overall_baseline
    const float* sb     = (const float*)d_in[9];   // spline_baseline
    float* out = (float*)d_out;
    int ncuts = in_sizes[1];

    k_padbase<<<NGOI, 160>>>(sb, goi);
    {
        dim3 grid((NGT + 255) / 256, (NC + 15) / 16);
        k_logits<<<grid, 256>>>(latent, wo, ob);
    }
    k_lse<<<NC, 256>>>();
    {
        dim3 grid(NGOI, CSPLIT);
        k_delta<<<grid, 256>>>(latent, hw, goi);
    }
    k_main<<<MAIN_BLOCKS, MAIN_THREADS>>>(coord, cxg, lcxg, gloc, ncuts);
    k_final<<<1, 256>>>(out);
}

// round 3
// speedup vs baseline: 2.5984x; 1.8425x over previous
#include <cuda_runtime.h>
#include <cuda_fp16.h>
#include <cstdint>

// Problem constants (fixed by the dataset)
#define NC   1000      // cells
#define NGOI 500       // genes of interest
#define NGT  5000      // total genes
#define NL   10        // latent dim
#define NK   129       // knots (NBINS+1)
#define RSH  136       // padded U row stride in halves (272B, 16B-aligned rows)
#define NPAIR (NC*NGOI)

#define MAIN_BLOCKS 1184
#define MAIN_THREADS 256
#define CSPLIT 8              // cell splits in k_delta
#define CPB (NC / CSPLIT)     // 125 cells per block

// ---------------- device scratch (static: no allocation allowed) -------------
__device__ float  g_logits[NC * NGT];                    // 20 MB (normalized in-place)
__device__ __half g_u[(size_t)NPAIR * RSH];              // 136 MB exp'd heights
__device__ float  g_A[NPAIR];                            // 2 MB  -log(trapezoid norm)
__device__ double g_part[MAIN_BLOCKS];

// ---------------- kernel: overall logits [NC x NGT] --------------------------
__global__ void k_logits(const float* __restrict__ latent,
                         const float* __restrict__ wo,
                         const float* __restrict__ ob) {
    __shared__ float lat[16 * NL];
    int g  = blockIdx.x * 256 + threadIdx.x;
    int c0 = blockIdx.y * 16;
    int t = threadIdx.x;
    if (t < 16 * NL) {
        int cc = c0 + t / NL;
        lat[t] = (cc < NC) ? latent[cc * NL + t % NL] : 0.f;
    }
    __syncthreads();
    if (g >= NGT) return;
    float w[NL];
#pragma unroll
    for (int l = 0; l < NL; l++) w[l] = wo[g * NL + l];
    float base = ob[g];
    int cmax = NC - c0; if (cmax > 16) cmax = 16;
    for (int c = 0; c < cmax; c++) {
        float a = base;
#pragma unroll
        for (int l = 0; l < NL; l++) a = fmaf(lat[c * NL + l], w[l], a);
        g_logits[(c0 + c) * NGT + g] = a;
    }
}

// ------- kernel: per-cell log-sum-exp over genes, normalize in place ---------
__global__ void k_lse() {
    int c = blockIdx.x;
    float s = 0.f;
    for (int g = threadIdx.x; g < NGT; g += 256)
        s += __expf(g_logits[c * NGT + g]);
    __shared__ float sh[8];
    __shared__ float slse;
#pragma unroll
    for (int o = 16; o; o >>= 1) s += __shfl_xor_sync(0xffffffffu, s, o);
    if ((threadIdx.x & 31) == 0) sh[threadIdx.x >> 5] = s;
    __syncthreads();
    if (threadIdx.x < 8) {
        s = sh[threadIdx.x];
#pragma unroll
        for (int o = 4; o; o >>= 1) s += __shfl_xor_sync(0xffu, s, o);
        if (threadIdx.x == 0) slse = __logf(s);
    }
    __syncthreads();
    float l = slse;
    for (int g = threadIdx.x; g < NGT; g += 256)
        g_logits[c * NGT + g] -= l;
}

// ------- kernel: per-pair exp'd spline heights + trapezoid log-norm ----------
// U[c*NGOI+j][k] = exp(sb[gene][k] + sum_l latent[c][l]*hw[gene][l][k])
// A[c*NGOI+j]    = -log( sum_k U - 0.5*U[0] - 0.5*U[128] )
__global__ void __launch_bounds__(256, 3) k_delta(const float* __restrict__ latent,
                                                  const float* __restrict__ hw,
                                                  const int*   __restrict__ goi,
                                                  const float* __restrict__ sb) {
    __shared__ float slat[CPB * 12];        // latent slice, stride 12
    int j = blockIdx.x;
    int gene = goi[j];
    int c0 = blockIdx.y * CPB;
    int tid = threadIdx.x;
    int w = tid >> 5, lane = tid & 31;

    // stage latent slice into smem
    for (int i = tid; i < CPB * NL; i += 256) {
        int cc = i / NL, l = i - cc * NL;
        slat[cc * 12 + l] = latent[(c0 + cc) * NL + l];
    }

    // per-lane knots: k4..k4+3; knot 128 redundant on all lanes
    int k4 = lane * 4;
    const float* bp = sb + (size_t)gene * NK;
    float b0 = bp[k4], b1 = bp[k4 + 1], b2 = bp[k4 + 2], b3 = bp[k4 + 3];
    float b4 = bp[128];
    const float* wp = hw + (size_t)gene * NL * NK;
    float W0[NL], W1[NL], W2[NL], W3[NL], W4[NL];
#pragma unroll
    for (int l = 0; l < NL; l++) {
        const float* r = wp + l * NK;
        W0[l] = r[k4];     W1[l] = r[k4 + 1];
        W2[l] = r[k4 + 2]; W3[l] = r[k4 + 3];
        W4[l] = r[128];
    }
    __syncthreads();

    for (int c = w; c < CPB; c += 8) {
        const float4 la = *(const float4*)&slat[c * 12];
        const float4 lb = *(const float4*)&slat[c * 12 + 4];
        const float2 lc = *(const float2*)&slat[c * 12 + 8];
        float lv[NL] = {la.x, la.y, la.z, la.w, lb.x, lb.y, lb.z, lb.w, lc.x, lc.y};
        float a0 = b0, a1 = b1, a2 = b2, a3 = b3, a4 = b4;
#pragma unroll
        for (int l = 0; l < NL; l++) {
            a0 = fmaf(lv[l], W0[l], a0);
            a1 = fmaf(lv[l], W1[l], a1);
            a2 = fmaf(lv[l], W2[l], a2);
            a3 = fmaf(lv[l], W3[l], a3);
            a4 = fmaf(lv[l], W4[l], a4);
        }
        float u0 = __expf(a0), u1 = __expf(a1);
        float u2 = __expf(a2), u3 = __expf(a3);
        float u4 = __expf(a4);                     // knot 128 (all lanes)

        float s = u0 + u1 + u2 + u3;
        if (lane == 0) s += 0.5f * (u4 - u0);      // +half top endpoint, halve bottom
#pragma unroll
        for (int o = 16; o; o >>= 1) s += __shfl_xor_sync(0xffffffffu, s, o);

        size_t p = (size_t)(c0 + c) * NGOI + j;
        __half2 h01 = __floats2half2_rn(u0, u1);
        __half2 h23 = __floats2half2_rn(u2, u3);
        uint2 st;
        st.x = *(const unsigned*)&h01;
        st.y = *(const unsigned*)&h23;
        *(uint2*)&g_u[p * RSH + k4] = st;
        if (lane == 31) g_u[p * RSH + 128] = __float2half_rn(u4);
        if (lane == 0)  g_A[p] = -__logf(s);
    }
}

// ---------------- kernel: per-cut interp + gather, one thread per cut --------
__global__ void __launch_bounds__(MAIN_THREADS) k_main(
        const float* __restrict__ coord,
        const int*   __restrict__ cxg,    // pair index [0, NPAIR)
        const int*   __restrict__ lcxg,   // cell x total-gene index [0, NC*NGT)
        int ncuts) {
    int stride = gridDim.x * blockDim.x;
    double acc = 0.0;
    const float C = 4.852030263919617f + 8.517193191416238f; // ln(128)+ln(5000)

    for (int i = blockIdx.x * blockDim.x + threadIdx.x; i < ncuts; i += stride) {
        int   p = __ldg(&cxg[i]);
        int   q = __ldg(&lcxg[i]);
        float x = __ldg(&coord[i]);

        float xs = fminf(fmaxf(x, 0.f), 0.999999f) * 128.f;
        int bi = (int)xs; if (bi > 127) bi = 127;
        float alpha = xs - (float)bi;

        size_t ub = (size_t)p * RSH + bi;
        float L = __half2float(g_u[ub]);
        float R = __half2float(g_u[ub + 1]);
        float nl = g_logits[q];
        float A  = g_A[p];

        acc += (double)(__logf(fmaf(alpha, R - L, L)) + A + C + nl);
    }

    // block reduction (deterministic)
    __shared__ double sh[MAIN_THREADS];
    sh[threadIdx.x] = acc;
    __syncthreads();
    for (int s = MAIN_THREADS / 2; s; s >>= 1) {
        if (threadIdx.x < s) sh[threadIdx.x] += sh[threadIdx.x + s];
        __syncthreads();
    }
    if (threadIdx.x == 0) g_part[blockIdx.x] = sh[0];
}

// ---------------- kernel: deterministic final reduce -------------------------
__global__ void k_final(float* __restrict__ out) {
    __shared__ double sh[256];
    double t = 0.0;
    for (int i = threadIdx.x; i < MAIN_BLOCKS; i += 256) t += g_part[i];
    sh[threadIdx.x] = t;
    __syncthreads();
    for (int s = 128; s; s >>= 1) {
        if (threadIdx.x < s) sh[threadIdx.x] += sh[threadIdx.x + s];
        __syncthreads();
    }
    if (threadIdx.x == 0) out[0] = (float)(-sh[0]);   // elbo = -sum(likelihood)
}

// ---------------- launch ------------------------------------------------------
extern "C" void kernel_launch(void* const* d_in, const int* in_sizes, int n_in,
                              void* d_out, int out_size) {
    const float* latent = (const float*)d_in[0];
    const float* coord  = (const float*)d_in[1];
    const int*   goi    = (const int*)  d_in[2];
    const int*   cxg    = (const int*)  d_in[3];   // cut_local_cellxgene_ix
    const int*   lcxg   = (const int*)  d_in[4];   // cut_localcellxgene_ix
    const float* hw     = (const float*)d_in[6];   // height_slope_w
    const float* wo     = (const float*)d_in[7];   // overall_slope_w
    const float* ob     = (const float*)d_in[8];   // overall_baseline
    const float* sb     = (const float*)d_in[9];   // spline_baseline
    float* out = (float*)d_out;
    int ncuts = in_sizes[1];

    {
        dim3 grid((NGT + 255) / 256, (NC + 15) / 16);
        k_logits<<<grid, 256>>>(latent, wo, ob);
    }
    k_lse<<<NC, 256>>>();
    {
        dim3 grid(NGOI, CSPLIT);
        k_delta<<<grid, 256>>>(latent, hw, goi, sb);
    }
    k_main<<<MAIN_BLOCKS, MAIN_THREADS>>>(coord, cxg, lcxg, ncuts);
    k_final<<<1, 256>>>(out);
}

// round 4
// speedup vs baseline: 2.6316x; 1.0128x over previous
#include <cuda_runtime.h>
#include <cstdint>

// Problem constants (fixed by the dataset)
#define NC   1000      // cells
#define NGOI 500       // genes of interest
#define NGT  5000      // total genes
#define NL   10        // latent dim
#define NK   129       // knots (NBINS+1)
#define NPAIR (NC*NGOI)

#define MAIN_BLOCKS 1184
#define MAIN_THREADS 256
#define CSPLIT 8              // cell splits in k_delta
#define CPB (NC / CSPLIT)     // 125 cells per block

// ---------------- device scratch (static: no allocation allowed) -------------
__device__ float  g_logits[NC * NGT];            // 20 MB (normalized in-place)
__device__ float  g_A[NPAIR];                    // 2 MB  -log(trapezoid norm)
// knot-major augmented weights: per (gene, bin) one 128B row of 32 floats:
// [ W[0..9][bi], b[bi], 0, 0, 0, 0, 0,  W[0..9][bi+1], b[bi+1], 0, 0, 0, 0, 0 ]
__device__ float  g_hwP[(size_t)NGOI * 128 * 32];   // 8.2 MB
__device__ float  g_latP[NC * 16];               // latent padded, slot10 = 1.0
__device__ double g_part[MAIN_BLOCKS];

// ---------------- prep: pad latent rows to 16, append 1.0 --------------------
__global__ void k_latpad(const float* __restrict__ latent) {
    int i = blockIdx.x * 256 + threadIdx.x;
    if (i >= NC * 16) return;
    int c = i >> 4, s = i & 15;
    float v = 0.f;
    if (s < NL) v = latent[c * NL + s];
    else if (s == NL) v = 1.f;
    g_latP[i] = v;
}

// ---------------- prep: build knot-major augmented weight rows ---------------
__global__ void k_hwprep(const float* __restrict__ hw,
                         const float* __restrict__ sb,
                         const int*   __restrict__ goi) {
    int j = blockIdx.x;                  // local gene
    int gene = goi[j];
    const float* wp = hw + (size_t)gene * NL * NK;
    const float* bp = sb + (size_t)gene * NK;
    for (int i = threadIdx.x; i < 128 * 32; i += 256) {
        int bi = i >> 5, slot = i & 31;
        float v = 0.f;
        int half = slot >> 4;            // 0: knot bi, 1: knot bi+1
        int s = slot & 15;
        int k = bi + half;
        if (s < NL) v = wp[s * NK + k];
        else if (s == NL) v = bp[k];
        g_hwP[((size_t)j * 128 + bi) * 32 + i % 32 - (i & 31) + slot] = v;  // = row*32+slot
    }
}

// ---------------- kernel: overall logits [NC x NGT] --------------------------
__global__ void k_logits(const float* __restrict__ latent,
                         const float* __restrict__ wo,
                         const float* __restrict__ ob) {
    __shared__ float lat[16 * NL];
    int g  = blockIdx.x * 256 + threadIdx.x;
    int c0 = blockIdx.y * 16;
    int t = threadIdx.x;
    if (t < 16 * NL) {
        int cc = c0 + t / NL;
        lat[t] = (cc < NC) ? latent[cc * NL + t % NL] : 0.f;
    }
    __syncthreads();
    if (g >= NGT) return;
    float w[NL];
#pragma unroll
    for (int l = 0; l < NL; l++) w[l] = wo[g * NL + l];
    float base = ob[g];
    int cmax = NC - c0; if (cmax > 16) cmax = 16;
    for (int c = 0; c < cmax; c++) {
        float a = base;
#pragma unroll
        for (int l = 0; l < NL; l++) a = fmaf(lat[c * NL + l], w[l], a);
        g_logits[(c0 + c) * NGT + g] = a;
    }
}

// ------- kernel: per-cell log-sum-exp over genes, normalize in place ---------
__global__ void k_lse() {
    int c = blockIdx.x;
    float s = 0.f;
    for (int g = threadIdx.x; g < NGT; g += 256)
        s += __expf(g_logits[c * NGT + g]);
    __shared__ float sh[8];
    __shared__ float slse;
#pragma unroll
    for (int o = 16; o; o >>= 1) s += __shfl_xor_sync(0xffffffffu, s, o);
    if ((threadIdx.x & 31) == 0) sh[threadIdx.x >> 5] = s;
    __syncthreads();
    if (threadIdx.x < 8) {
        s = sh[threadIdx.x];
#pragma unroll
        for (int o = 4; o; o >>= 1) s += __shfl_xor_sync(0xffu, s, o);
        if (threadIdx.x == 0) slse = __logf(s);
    }
    __syncthreads();
    float l = slse;
    for (int g = threadIdx.x; g < NGT; g += 256)
        g_logits[c * NGT + g] -= l;
}

// ------- kernel: per-pair trapezoid log-norm A = -log(s) ---------------------
// s = sum_k u_k - 0.5*(u_0 + u_128), u_k = exp(sb[gene][k] + sum_l lat*hw)
__global__ void __launch_bounds__(256, 3) k_delta(const float* __restrict__ latent,
                                                  const float* __restrict__ hw,
                                                  const int*   __restrict__ goi,
                                                  const float* __restrict__ sb) {
    __shared__ float slat[CPB * 12];        // latent slice, stride 12
    int j = blockIdx.x;
    int gene = goi[j];
    int c0 = blockIdx.y * CPB;
    int tid = threadIdx.x;
    int w = tid >> 5, lane = tid & 31;

    for (int i = tid; i < CPB * NL; i += 256) {
        int cc = i / NL, l = i - cc * NL;
        slat[cc * 12 + l] = latent[(c0 + cc) * NL + l];
    }

    // per-lane knots: k4..k4+3; knot 128 redundant on all lanes
    int k4 = lane * 4;
    const float* bp = sb + (size_t)gene * NK;
    float b0 = bp[k4], b1 = bp[k4 + 1], b2 = bp[k4 + 2], b3 = bp[k4 + 3];
    float b4 = bp[128];
    const float* wp = hw + (size_t)gene * NL * NK;
    float W0[NL], W1[NL], W2[NL], W3[NL], W4[NL];
#pragma unroll
    for (int l = 0; l < NL; l++) {
        const float* r = wp + l * NK;
        W0[l] = r[k4];     W1[l] = r[k4 + 1];
        W2[l] = r[k4 + 2]; W3[l] = r[k4 + 3];
        W4[l] = r[128];
    }
    __syncthreads();

    for (int c = w; c < CPB; c += 8) {
        const float4 la = *(const float4*)&slat[c * 12];
        const float4 lb = *(const float4*)&slat[c * 12 + 4];
        const float2 lc = *(const float2*)&slat[c * 12 + 8];
        float lv[NL] = {la.x, la.y, la.z, la.w, lb.x, lb.y, lb.z, lb.w, lc.x, lc.y};
        float a0 = b0, a1 = b1, a2 = b2, a3 = b3, a4 = b4;
#pragma unroll
        for (int l = 0; l < NL; l++) {
            a0 = fmaf(lv[l], W0[l], a0);
            a1 = fmaf(lv[l], W1[l], a1);
            a2 = fmaf(lv[l], W2[l], a2);
            a3 = fmaf(lv[l], W3[l], a3);
            a4 = fmaf(lv[l], W4[l], a4);
        }
        float u0 = __expf(a0), u1 = __expf(a1);
        float u2 = __expf(a2), u3 = __expf(a3);
        float u4 = __expf(a4);                     // knot 128 (all lanes)

        float s = u0 + u1 + u2 + u3;
        if (lane == 0) s += 0.5f * (u4 - u0);      // +half top endpoint, halve bottom
#pragma unroll
        for (int o = 16; o; o >>= 1) s += __shfl_xor_sync(0xffffffffu, s, o);

        if (lane == 0) g_A[(size_t)(c0 + c) * NGOI + j] = -__logf(s);
    }
}

// ---------------- kernel: per-cut exact fp32 interp, one thread per cut ------
__global__ void __launch_bounds__(MAIN_THREADS) k_main(
        const float* __restrict__ coord,
        const int*   __restrict__ cxg,    // pair index [0, NPAIR)
        const int*   __restrict__ lcxg,   // cell x total-gene index
        const int*   __restrict__ gloc,   // local gene index [0, NGOI)
        int ncuts) {
    int stride = gridDim.x * blockDim.x;
    double acc = 0.0;
    const float C = 4.852030263919617f + 8.517193191416238f; // ln(128)+ln(5000)

    for (int i = blockIdx.x * blockDim.x + threadIdx.x; i < ncuts; i += stride) {
        int   p  = __ldg(&cxg[i]);
        int   q  = __ldg(&lcxg[i]);
        int   gl = __ldg(&gloc[i]);
        float x  = __ldg(&coord[i]);
        int cell = p / NGOI;

        float xs = fminf(fmaxf(x, 0.f), 0.999999f) * 128.f;
        int bi = (int)xs; if (bi > 127) bi = 127;
        float alpha = xs - (float)bi;

        // latent row (L1-hot, 64 KB), slot 10 = 1.0 multiplies the baseline
        const float4* lp = (const float4*)&g_latP[cell * 16];
        float4 v0 = __ldg(&lp[0]);
        float4 v1 = __ldg(&lp[1]);
        float4 v2 = __ldg(&lp[2]);

        const float4* rp = (const float4*)&g_hwP[((size_t)gl * 128 + bi) * 32];
        float4 wl0 = __ldg(&rp[0]);
        float4 wl1 = __ldg(&rp[1]);
        float4 wl2 = __ldg(&rp[2]);
        float4 wr0 = __ldg(&rp[4]);
        float4 wr1 = __ldg(&rp[5]);
        float4 wr2 = __ldg(&rp[6]);

        float hL = v0.x*wl0.x + v0.y*wl0.y + v0.z*wl0.z + v0.w*wl0.w
                 + v1.x*wl1.x + v1.y*wl1.y + v1.z*wl1.z + v1.w*wl1.w
                 + v2.x*wl2.x + v2.y*wl2.y + v2.z*wl2.z;
        float hR = v0.x*wr0.x + v0.y*wr0.y + v0.z*wr0.z + v0.w*wr0.w
                 + v1.x*wr1.x + v1.y*wr1.y + v1.z*wr1.z + v1.w*wr1.w
                 + v2.x*wr2.x + v2.y*wr2.y + v2.z*wr2.z;

        float L = __expf(hL);
        float R = __expf(hR);
        float nl = __ldg(&g_logits[q]);
        float A  = __ldg(&g_A[p]);

        acc += (double)(__logf(fmaf(alpha, R - L, L)) + A + C + nl);
    }

    __shared__ double sh[MAIN_THREADS];
    sh[threadIdx.x] = acc;
    __syncthreads();
    for (int s = MAIN_THREADS / 2; s; s >>= 1) {
        if (threadIdx.x < s) sh[threadIdx.x] += sh[threadIdx.x + s];
        __syncthreads();
    }
    if (threadIdx.x == 0) g_part[blockIdx.x] = sh[0];
}

// ---------------- kernel: deterministic final reduce -------------------------
__global__ void k_final(float* __restrict__ out) {
    __shared__ double sh[256];
    double t = 0.0;
    for (int i = threadIdx.x; i < MAIN_BLOCKS; i += 256) t += g_part[i];
    sh[threadIdx.x] = t;
    __syncthreads();
    for (int s = 128; s; s >>= 1) {
        if (threadIdx.x < s) sh[threadIdx.x] += sh[threadIdx.x + s];
        __syncthreads();
    }
    if (threadIdx.x == 0) out[0] = (float)(-sh[0]);   // elbo = -sum(likelihood)
}

// ---------------- launch ------------------------------------------------------
extern "C" void kernel_launch(void* const* d_in, const int* in_sizes, int n_in,
                              void* d_out, int out_size) {
    const float* latent = (const float*)d_in[0];
    const float* coord  = (const float*)d_in[1];
    const int*   goi    = (const int*)  d_in[2];
    const int*   cxg    = (const int*)  d_in[3];   // cut_local_cellxgene_ix
    const int*   lcxg   = (const int*)  d_in[4];   // cut_localcellxgene_ix
    const int*   gloc   = (const int*)  d_in[5];   // cut_local_gene_ix
    const float* hw     = (const float*)d_in[6];   // height_slope_w
    const float* wo     = (const float*)d_in[7];   // overall_slope_w
    const float* ob     = (const float*)d_in[8];   // overall_baseline
    const float* sb     = (const float*)d_in[9];   // spline_baseline
    float* out = (float*)d_out;
    int ncuts = in_sizes[1];

    k_latpad<<<(NC * 16 + 255) / 256, 256>>>(latent);
    k_hwprep<<<NGOI, 256>>>(hw, sb, goi);
    {
        dim3 grid((NGT + 255) / 256, (NC + 15) / 16);
        k_logits<<<grid, 256>>>(latent, wo, ob);
    }
    k_lse<<<NC, 256>>>();
    {
        dim3 grid(NGOI, CSPLIT);
        k_delta<<<grid, 256>>>(latent, hw, goi, sb);
    }
    k_main<<<MAIN_BLOCKS, MAIN_THREADS>>>(coord, cxg, lcxg, gloc, ncuts);
    k_final<<<1, 256>>>(out);
}